// round 6
// baseline (speedup 1.0000x reference)
#include <cuda_runtime.h>
#include <cuda_bf16.h>
#include <math.h>

#define N_NODES 200000
#define N_EDGES 1250000
#define D 64
#define G 128
#define NB 196          // ceil(N_NODES/1024)

typedef unsigned long long ull;

// ---------------- device scratch (static; no allocation) ----------------
__device__ int   g_is64;
__device__ int   g_cnt[N_NODES];
__device__ int   g_rowptr[N_NODES + 1];
__device__ int   g_scan[N_NODES];
__device__ int   g_bsum[256];
__device__ int   g_esrc[N_EDGES];
__device__ float g_z[N_NODES * D];
__device__ float g_h[N_NODES * D];
__device__ float g_pool[G * 2 * D];
__device__ int   g_gb[G + 1];

// ---------------- packed f32x2 helpers ----------------
__device__ __forceinline__ ull f32x2_dup(float x) {
    ull r;
    asm("mov.b64 %0, {%1, %1};" : "=l"(r) : "f"(x));
    return r;
}
__device__ __forceinline__ void f32x2_fma(ull& d, ull a, ull b) {
    asm("fma.rn.f32x2 %0, %1, %2, %0;" : "+l"(d) : "l"(a), "l"(b));
}
__device__ __forceinline__ float2 f32x2_unpack(ull a) {
    float lo, hi;
    asm("mov.b64 {%0, %1}, %2;" : "=f"(lo), "=f"(hi) : "l"(a));
    return make_float2(lo, hi);
}

__device__ __forceinline__ int load_idx(const void* p, int i) {
    if (g_is64) return (int)((const long long*)p)[i];
    return ((const int*)p)[i];
}

// ---------------- init: zero histogram + dtype detect ----------------
__global__ void k_init(const int* __restrict__ e) {
    int i = blockIdx.x * blockDim.x + threadIdx.x;
    if (i < N_NODES) g_cnt[i] = 0;
    if (i == 0) {
        int all0 = 1;
        #pragma unroll 1
        for (int j = 0; j < 64; j++)
            if (e[2 * j + 1] != 0) { all0 = 0; break; }
        g_is64 = all0;
    }
}

// ---------------- count (+ graph-boundary search in last block) ----------------
__global__ void k_count(const void* __restrict__ eidx, const void* __restrict__ batch,
                        int nEB) {
    if ((int)blockIdx.x == nEB) {
        int g = threadIdx.x;
        if (g > G) return;
        int lo = 0, hi = N_NODES;
        while (lo < hi) {
            int mid = (lo + hi) >> 1;
            if (load_idx(batch, mid) < g) lo = mid + 1; else hi = mid;
        }
        g_gb[g] = lo;
        return;
    }
    int e = blockIdx.x * blockDim.x + threadIdx.x;
    if (e < N_EDGES) {
        int d = load_idx(eidx, N_EDGES + e);
        atomicAdd(&g_cnt[d], 1);
    }
}

// ---------------- scan stage A: per-1024-block scan ----------------
__global__ void k_scanA() {
    __shared__ int sh[1024];
    int b = blockIdx.x, t = threadIdx.x;
    int i = b * 1024 + t;
    int v = (i < N_NODES) ? g_cnt[i] : 0;
    sh[t] = v;
    __syncthreads();
    #pragma unroll
    for (int o = 1; o < 1024; o <<= 1) {
        int u = (t >= o) ? sh[t - o] : 0;
        __syncthreads();
        sh[t] += u;
        __syncthreads();
    }
    if (i < N_NODES) g_scan[i] = sh[t] - v;   // exclusive within block
    if (t == 1023) g_bsum[b] = sh[1023];
}

// ---------------- scan stage C (fused B): every block redundantly scans bsums ----------------
__global__ void k_scanC() {
    __shared__ int sh[256];
    int t = threadIdx.x;
    int v = (t < NB) ? g_bsum[t] : 0;
    sh[t] = v;
    __syncthreads();
    #pragma unroll
    for (int o = 1; o < 256; o <<= 1) {
        int u = (t >= o) ? sh[t - o] : 0;
        __syncthreads();
        sh[t] += u;
        __syncthreads();
    }
    int i = blockIdx.x * 256 + t;
    if (i < N_NODES) {
        int b = i >> 10;
        int ex = (b == 0) ? 0 : sh[b - 1];
        int val = g_scan[i] + ex;
        g_rowptr[i] = val;
        g_cnt[i] = val;   // write cursor for scatter
        if (i == N_NODES - 1) g_rowptr[N_NODES] = sh[NB - 1];
    }
}

__global__ void k_scatter(const void* __restrict__ eidx) {
    int e = blockIdx.x * blockDim.x + threadIdx.x;
    if (e < N_EDGES) {
        int dst = load_idx(eidx, N_EDGES + e);
        int src = load_idx(eidx, e);
        int pos = atomicAdd(&g_cnt[dst], 1);
        g_esrc[pos] = src;
    }
}

// ---------------- aggregation: z[i] = x[i] + sum_{j->i} x[j] (4-way unrolled) ----------------
__global__ void __launch_bounds__(256) k_agg(const float* __restrict__ xin,
                                             float* __restrict__ zout) {
    int warp = (blockIdx.x * blockDim.x + threadIdx.x) >> 5;
    int lane = threadIdx.x & 31;
    if (warp >= N_NODES) return;
    const float2* __restrict__ x2 = (const float2*)xin;
    float2 a = x2[warp * 32 + lane];
    int e = g_rowptr[warp], end = g_rowptr[warp + 1];
    for (; e + 4 <= end; e += 4) {
        int s0 = g_esrc[e + 0], s1 = g_esrc[e + 1];
        int s2 = g_esrc[e + 2], s3 = g_esrc[e + 3];
        float2 v0 = __ldg(&x2[s0 * 32 + lane]);
        float2 v1 = __ldg(&x2[s1 * 32 + lane]);
        float2 v2 = __ldg(&x2[s2 * 32 + lane]);
        float2 v3 = __ldg(&x2[s3 * 32 + lane]);
        a.x += (v0.x + v1.x) + (v2.x + v3.x);
        a.y += (v0.y + v1.y) + (v2.y + v3.y);
    }
    for (; e < end; e++) {
        int s = g_esrc[e];
        float2 v = __ldg(&x2[s * 32 + lane]);
        a.x += v.x; a.y += v.y;
    }
    ((float2*)zout)[warp * 32 + lane] = a;
}

// ---------------- node MLP (thread-per-node, f32x2 FMA, LDS.128 weights) ----------------
// h = [relu]( relu(z@w1+b1) @ w2 + b2 )
template <bool RELU_OUT>
__global__ void __launch_bounds__(128) k_mlp(const float* __restrict__ zin,
                                             float* __restrict__ hout,
                                             const float* __restrict__ w1,
                                             const float* __restrict__ b1,
                                             const float* __restrict__ w2,
                                             const float* __restrict__ b2) {
    __shared__ __align__(16) float w1s[64 * 64];
    __shared__ __align__(16) float w2s[64 * 64];
    __shared__ __align__(16) float b1s[64], b2s[64];
    int t = threadIdx.x;
    {
        const float4* s1 = (const float4*)w1;
        const float4* s2 = (const float4*)w2;
        float4* d1 = (float4*)w1s;
        float4* d2 = (float4*)w2s;
        #pragma unroll
        for (int i = t; i < 1024; i += 128) { d1[i] = s1[i]; d2[i] = s2[i]; }
    }
    if (t < 64) { b1s[t] = b1[t]; b2s[t] = b2[t]; }
    __syncthreads();

    for (int node = blockIdx.x * 128 + t; node < N_NODES; node += gridDim.x * 128) {
        // z row in registers
        float zf[64];
        {
            const float4* z4 = (const float4*)(zin + node * 64);
            #pragma unroll
            for (int i = 0; i < 16; i++) {
                float4 v = z4[i];
                zf[4 * i + 0] = v.x; zf[4 * i + 1] = v.y;
                zf[4 * i + 2] = v.z; zf[4 * i + 3] = v.w;
            }
        }

        ull acc[32];

        // ---- layer 1: relu(z @ w1 + b1), result back into zf ----
        {
            const ull* bp = (const ull*)b1s;
            #pragma unroll
            for (int j = 0; j < 32; j++) acc[j] = bp[j];
            #pragma unroll 4
            for (int k = 0; k < 64; k++) {
                ull zz = f32x2_dup(zf[k]);
                const ulonglong2* wr = (const ulonglong2*)(w1s + (k << 6));
                #pragma unroll
                for (int j = 0; j < 16; j++) {
                    ulonglong2 w = wr[j];
                    f32x2_fma(acc[2 * j + 0], zz, w.x);
                    f32x2_fma(acc[2 * j + 1], zz, w.y);
                }
            }
            #pragma unroll
            for (int j = 0; j < 32; j++) {
                float2 p = f32x2_unpack(acc[j]);
                zf[2 * j + 0] = fmaxf(p.x, 0.f);
                zf[2 * j + 1] = fmaxf(p.y, 0.f);
            }
        }

        // ---- layer 2: zf @ w2 + b2 ----
        {
            const ull* bp = (const ull*)b2s;
            #pragma unroll
            for (int j = 0; j < 32; j++) acc[j] = bp[j];
            #pragma unroll 4
            for (int k = 0; k < 64; k++) {
                ull zz = f32x2_dup(zf[k]);
                const ulonglong2* wr = (const ulonglong2*)(w2s + (k << 6));
                #pragma unroll
                for (int j = 0; j < 16; j++) {
                    ulonglong2 w = wr[j];
                    f32x2_fma(acc[2 * j + 0], zz, w.x);
                    f32x2_fma(acc[2 * j + 1], zz, w.y);
                }
            }
        }

        float4* h4 = (float4*)(hout + node * 64);
        #pragma unroll
        for (int j = 0; j < 16; j++) {
            float2 p0 = f32x2_unpack(acc[2 * j + 0]);
            float2 p1 = f32x2_unpack(acc[2 * j + 1]);
            if (RELU_OUT) {
                p0.x = fmaxf(p0.x, 0.f); p0.y = fmaxf(p0.y, 0.f);
                p1.x = fmaxf(p1.x, 0.f); p1.y = fmaxf(p1.y, 0.f);
            }
            h4[j] = make_float4(p0.x, p0.y, p1.x, p1.y);
        }
    }
}

// ---------------- pooling: per-graph sum & max ----------------
__global__ void __launch_bounds__(512) k_pool(const float* __restrict__ h) {
    __shared__ float ssum[8][64], smax[8][64];
    int g = blockIdx.x, t = threadIdx.x;
    int col = t & 63, ch = t >> 6;
    int beg = g_gb[g], end = g_gb[g + 1];
    float s = 0.f, m = -INFINITY;
    for (int i = beg + ch; i < end; i += 8) {
        float v = h[i * 64 + col];
        s += v; m = fmaxf(m, v);
    }
    ssum[ch][col] = s; smax[ch][col] = m;
    __syncthreads();
    if (t < 64) {
        float S = 0.f, M = -INFINITY;
        #pragma unroll
        for (int c = 0; c < 8; c++) { S += ssum[c][t]; M = fmaxf(M, smax[c][t]); }
        g_pool[g * 128 + t]      = S;
        g_pool[g * 128 + 64 + t] = M;
    }
}

// ---------------- head MLP: 128 -> 128 -> 64 -> 32 -> 16 -> 1, SiLU ----------------
__device__ __forceinline__ float silu(float x) { return x / (1.f + expf(-x)); }

__global__ void __launch_bounds__(128) k_head(float* __restrict__ out,
        const float* __restrict__ w0, const float* __restrict__ b0,
        const float* __restrict__ w1, const float* __restrict__ b1,
        const float* __restrict__ w2, const float* __restrict__ b2,
        const float* __restrict__ w3, const float* __restrict__ b3,
        const float* __restrict__ w4, const float* __restrict__ b4) {
    __shared__ float bufA[128], bufB[128];
    int g = blockIdx.x, t = threadIdx.x;
    bufA[t] = g_pool[g * 128 + t];
    __syncthreads();
    {
        float a = b0[t];
        #pragma unroll 8
        for (int k = 0; k < 128; k++) a = fmaf(bufA[k], w0[k * 128 + t], a);
        bufB[t] = silu(a);
    }
    __syncthreads();
    if (t < 64) {
        float a = b1[t];
        #pragma unroll 8
        for (int k = 0; k < 128; k++) a = fmaf(bufB[k], w1[k * 64 + t], a);
        bufA[t] = silu(a);
    }
    __syncthreads();
    if (t < 32) {
        float a = b2[t];
        #pragma unroll 8
        for (int k = 0; k < 64; k++) a = fmaf(bufA[k], w2[k * 32 + t], a);
        bufB[t] = silu(a);
    }
    __syncthreads();
    if (t < 16) {
        float a = b3[t];
        #pragma unroll
        for (int k = 0; k < 32; k++) a = fmaf(bufB[k], w3[k * 16 + t], a);
        bufA[t] = silu(a);
    }
    __syncthreads();
    if (t == 0) {
        float a = b4[0];
        #pragma unroll
        for (int k = 0; k < 16; k++) a = fmaf(bufA[k], w4[k], a);
        out[g] = a;
    }
}

// ---------------- launch ----------------
extern "C" void kernel_launch(void* const* d_in, const int* in_sizes, int n_in,
                              void* d_out, int out_size) {
    const float* x     = (const float*)d_in[0];
    const void*  eidx  = d_in[1];
    const void*  batch = d_in[2];
    const float* c1w1 = (const float*)d_in[3];
    const float* c1b1 = (const float*)d_in[4];
    const float* c1w2 = (const float*)d_in[5];
    const float* c1b2 = (const float*)d_in[6];
    const float* c2w1 = (const float*)d_in[7];
    const float* c2b1 = (const float*)d_in[8];
    const float* c2w2 = (const float*)d_in[9];
    const float* c2b2 = (const float*)d_in[10];
    const float* hw0 = (const float*)d_in[11];
    const float* hb0 = (const float*)d_in[12];
    const float* hw1 = (const float*)d_in[13];
    const float* hb1 = (const float*)d_in[14];
    const float* hw2 = (const float*)d_in[15];
    const float* hb2 = (const float*)d_in[16];
    const float* hw3 = (const float*)d_in[17];
    const float* hb3 = (const float*)d_in[18];
    const float* hw4 = (const float*)d_in[19];
    const float* hb4 = (const float*)d_in[20];
    float* out = (float*)d_out;

    void *pz, *ph;
    cudaGetSymbolAddress(&pz, g_z);
    cudaGetSymbolAddress(&ph, g_h);
    float* zbuf = (float*)pz;
    float* hbuf = (float*)ph;

    const int EB = (N_EDGES + 255) / 256;      // 4883
    const int aggBlocks = (N_NODES * 32 + 255) / 256;
    const int mlpBlocks = 592;                 // grid-stride

    k_init<<<(N_NODES + 255) / 256, 256>>>((const int*)eidx);
    k_count<<<EB + 1, 256>>>(eidx, batch, EB);
    k_scanA<<<NB, 1024>>>();
    k_scanC<<<(N_NODES + 255) / 256, 256>>>();
    k_scatter<<<EB, 256>>>(eidx);

    k_agg<<<aggBlocks, 256>>>(x, zbuf);
    k_mlp<true><<<mlpBlocks, 128>>>(zbuf, hbuf, c1w1, c1b1, c1w2, c1b2);
    k_agg<<<aggBlocks, 256>>>(hbuf, zbuf);
    k_mlp<false><<<mlpBlocks, 128>>>(zbuf, hbuf, c2w1, c2b1, c2w2, c2b2);

    k_pool<<<G, 512>>>(hbuf);
    k_head<<<G, 128>>>(out, hw0, hb0, hw1, hb1, hw2, hb2, hw3, hb3, hw4, hb4);
}